// round 8
// baseline (speedup 1.0000x reference)
#include <cuda_runtime.h>
#include <cuda_bf16.h>
#include <cstdint>

#define DIM 512
#define HEADS 8
#define DHEAD 64
#define BATCH 4
#define NSEQ 2048
#define ROWS (BATCH * NSEQ)

__device__ __nv_bfloat16 g_xnh[ROWS * DIM], g_xnl[ROWS * DIM];
__device__ __nv_bfloat16 g_ath[ROWS * DIM], g_atl[ROWS * DIM];
__device__ __nv_bfloat16 g_wqh[DIM * DIM], g_wql[DIM * DIM];
__device__ __nv_bfloat16 g_wkh[DIM * DIM], g_wkl[DIM * DIM];
__device__ __nv_bfloat16 g_wvh[DIM * DIM], g_wvl[DIM * DIM];
__device__ __nv_bfloat16 g_woh[DIM * DIM], g_wol[DIM * DIM];
__device__ int8_t g_q1[ROWS * DIM], g_q2[ROWS * DIM];
__device__ int8_t g_k1[ROWS * DIM], g_k2[ROWS * DIM];
__device__ float  g_qdq[HEADS * ROWS], g_kdq[HEADS * ROWS];
__device__ float  g_v[ROWS * DIM];
__device__ int8_t g_vt1[BATCH * HEADS * DHEAD * NSEQ], g_vt2[BATCH * HEADS * DHEAD * NSEQ];
__device__ int    g_vamax[DIM];

__device__ __forceinline__ uint32_t smem_u32(const void* p) {
    uint32_t a;
    asm("{ .reg .u64 t; cvta.to.shared.u64 t, %1; cvt.u32.u64 %0, t; }" : "=r"(a) : "l"(p));
    return a;
}
__device__ __forceinline__ void ldsm4(uint32_t* r, uint32_t a) {
    asm volatile("ldmatrix.sync.aligned.m8n8.x4.shared.b16 {%0,%1,%2,%3}, [%4];"
                 : "=r"(r[0]), "=r"(r[1]), "=r"(r[2]), "=r"(r[3]) : "r"(a));
}
__device__ __forceinline__ void mma16816(float* c, const uint32_t* a, const uint32_t* b) {
    asm volatile("mma.sync.aligned.m16n8k16.row.col.f32.bf16.bf16.f32 "
                 "{%0,%1,%2,%3}, {%4,%5,%6,%7}, {%8,%9}, {%0,%1,%2,%3};"
                 : "+f"(c[0]), "+f"(c[1]), "+f"(c[2]), "+f"(c[3])
                 : "r"(a[0]), "r"(a[1]), "r"(a[2]), "r"(a[3]), "r"(b[0]), "r"(b[1]));
}
__device__ __forceinline__ void imma(int* c, const uint32_t* a, const uint32_t* b) {
    asm volatile("mma.sync.aligned.m16n8k32.row.col.s32.s8.s8.s32 "
                 "{%0,%1,%2,%3}, {%4,%5,%6,%7}, {%8,%9}, {%0,%1,%2,%3};"
                 : "+r"(c[0]), "+r"(c[1]), "+r"(c[2]), "+r"(c[3])
                 : "r"(a[0]), "r"(a[1]), "r"(a[2]), "r"(a[3]), "r"(b[0]), "r"(b[1]));
}
__device__ __forceinline__ void cpa16(uint32_t d, const void* s) {
    asm volatile("cp.async.cg.shared.global [%0], [%1], 16;" :: "r"(d), "l"(s));
}
#define CP_COMMIT() asm volatile("cp.async.commit_group;")
#define CP_WAIT(n)  asm volatile("cp.async.wait_group %0;" :: "n"(n))
__device__ __forceinline__ void sts16(uint32_t a, uint32_t v) {
    asm volatile("st.shared.u16 [%0], %1;" :: "r"(a), "r"(v));
}
__device__ __forceinline__ uint32_t bf2pack(float a, float b) {
    __nv_bfloat162 t = __floats2bfloat162_rn(a, b);
    return *reinterpret_cast<uint32_t*>(&t);
}
__device__ __forceinline__ float bfres(float a) {
    __nv_bfloat16 h = __float2bfloat16_rn(a);
    return a - __bfloat162float(h);
}
#define INV254 (1.f / 254.f)
#define SPQ (127.f / 16.f)

__global__ void zero_amax() { g_vamax[threadIdx.x] = 0; }

// ---------- LayerNorm -> bf16 hi/lo ----------
__global__ __launch_bounds__(256) void ln_kernel(const float* __restrict__ x,
                                                 const float* __restrict__ w,
                                                 const float* __restrict__ b) {
    __shared__ float sb1[8], sb2[8];
    int row = blockIdx.x, t = threadIdx.x;
    const float* xr = x + (size_t)row * DIM;
    float v0 = xr[t], v1 = xr[t + 256];
    float s = v0 + v1, ss = v0 * v0 + v1 * v1;
    #pragma unroll
    for (int o = 16; o > 0; o >>= 1) {
        s  += __shfl_xor_sync(~0u, s, o);
        ss += __shfl_xor_sync(~0u, ss, o);
    }
    int lane = t & 31, wd = t >> 5;
    if (lane == 0) { sb1[wd] = s; sb2[wd] = ss; }
    __syncthreads();
    if (wd == 0) {
        float r1 = (lane < 8) ? sb1[lane] : 0.f, r2 = (lane < 8) ? sb2[lane] : 0.f;
        #pragma unroll
        for (int o = 4; o > 0; o >>= 1) {
            r1 += __shfl_xor_sync(~0u, r1, o);
            r2 += __shfl_xor_sync(~0u, r2, o);
        }
        if (lane == 0) { sb1[0] = r1; sb2[0] = r2; }
    }
    __syncthreads();
    float mu = sb1[0] * (1.f / DIM);
    float var = sb2[0] * (1.f / DIM) - mu * mu;
    float inv = rsqrtf(var + 1e-5f);
    float o0 = (v0 - mu) * inv * w[t] + b[t];
    float o1 = (v1 - mu) * inv * w[t + 256] + b[t + 256];
    size_t base = (size_t)row * DIM;
    __nv_bfloat16 h0 = __float2bfloat16_rn(o0), h1 = __float2bfloat16_rn(o1);
    g_xnh[base + t] = h0; g_xnh[base + t + 256] = h1;
    g_xnl[base + t] = __float2bfloat16_rn(o0 - __bfloat162float(h0));
    g_xnl[base + t + 256] = __float2bfloat16_rn(o1 - __bfloat162float(h1));
}

// ---------- weight-norm -> bf16 hi/lo ----------
__global__ __launch_bounds__(256) void wnorm_kernel(const float* __restrict__ wv_v,
                                                    const float* __restrict__ wv_g) {
    __shared__ float sbuf[8];
    int row = blockIdx.x, t = threadIdx.x;
    const float* vr = wv_v + (size_t)row * DIM;
    float v0 = vr[t], v1 = vr[t + 256];
    float ss = v0 * v0 + v1 * v1;
    #pragma unroll
    for (int o = 16; o > 0; o >>= 1) ss += __shfl_xor_sync(~0u, ss, o);
    int lane = t & 31, wd = t >> 5;
    if (lane == 0) sbuf[wd] = ss;
    __syncthreads();
    if (wd == 0) {
        float r = (lane < 8) ? sbuf[lane] : 0.f;
        #pragma unroll
        for (int o = 4; o > 0; o >>= 1) r += __shfl_xor_sync(~0u, r, o);
        if (lane == 0) sbuf[0] = r;
    }
    __syncthreads();
    float sc = wv_g[row] * rsqrtf(sbuf[0]);
    float o0 = v0 * sc, o1 = v1 * sc;
    size_t base = (size_t)row * DIM;
    __nv_bfloat16 h0 = __float2bfloat16_rn(o0), h1 = __float2bfloat16_rn(o1);
    g_wvh[base + t] = h0; g_wvh[base + t + 256] = h1;
    g_wvl[base + t] = __float2bfloat16_rn(o0 - __bfloat162float(h0));
    g_wvl[base + t + 256] = __float2bfloat16_rn(o1 - __bfloat162float(h1));
}

__global__ __launch_bounds__(256) void conv_kernel(const float* __restrict__ src,
                                                   __nv_bfloat16* __restrict__ hi,
                                                   __nv_bfloat16* __restrict__ lo, int n) {
    int i = blockIdx.x * 256 + threadIdx.x;
    if (i < n) {
        float f = src[i];
        __nv_bfloat16 h = __float2bfloat16_rn(f);
        hi[i] = h;
        lo[i] = __float2bfloat16_rn(f - __bfloat162float(h));
    }
}

// ---------- GEMM (bf16 3-split).  MODE 0: float out. 1: int8 2-slice quant. 2: float + col amax ----------
#define GP 144
#define T_SZ (128 * GP)
#define G_SMEM (4 * T_SZ)

template <int MODE>
__global__ __launch_bounds__(256, 2)
void gemm_bf3(const __nv_bfloat16* __restrict__ Ah, const __nv_bfloat16* __restrict__ Al,
              const __nv_bfloat16* __restrict__ Bh, const __nv_bfloat16* __restrict__ Bl,
              float* __restrict__ Cf, int8_t* __restrict__ O1, int8_t* __restrict__ O2,
              float* __restrict__ dqout, float scale) {
    extern __shared__ char sm[];
    uint32_t sb = smem_u32(sm);
    int tid = threadIdx.x, lane = tid & 31, wd = tid >> 5;
    int wm = wd & 3, wn = wd >> 2;
    int tm = blockIdx.y * 128, tn = blockIdx.x * 128;

    float c[2][8][4];
    #pragma unroll
    for (int i = 0; i < 2; i++)
        #pragma unroll
        for (int j = 0; j < 8; j++)
            #pragma unroll
            for (int e = 0; e < 4; e++) c[i][j][e] = 0.f;

    for (int kc = 0; kc < 8; kc++) {
        if (kc) __syncthreads();
        int k0 = kc * 64;
        #pragma unroll
        for (int u = 0; u < 4; u++) {
            int e = tid + u * 256;
            int r = e >> 3, c8 = (e & 7) * 8;
            uint32_t d = sb + (uint32_t)r * GP + c8 * 2;
            size_t ga = (size_t)(tm + r) * DIM + k0 + c8;
            size_t gb = (size_t)(tn + r) * DIM + k0 + c8;
            cpa16(d, &Ah[ga]); cpa16(d + T_SZ, &Al[ga]);
            cpa16(d + 2 * T_SZ, &Bh[gb]); cpa16(d + 3 * T_SZ, &Bl[gb]);
        }
        CP_COMMIT(); CP_WAIT(0);
        __syncthreads();
        #pragma unroll
        for (int ks = 0; ks < 4; ks++) {
            uint32_t ah[2][4], al[2][4];
            uint32_t acol = ks * 32 + ((lane >> 4) << 4);
            #pragma unroll
            for (int mt = 0; mt < 2; mt++) {
                uint32_t arow = wm * 32 + mt * 16 + (lane & 15);
                ldsm4(ah[mt], sb + arow * GP + acol);
                ldsm4(al[mt], sb + T_SZ + arow * GP + acol);
            }
            uint32_t bro = ((lane >> 4) << 3) + (lane & 7);
            uint32_t bcol = ks * 32 + (((lane >> 3) & 1) << 4);
            #pragma unroll
            for (int p = 0; p < 4; p++) {
                uint32_t nrow = wn * 64 + p * 16 + bro;
                uint32_t bh[4], bl[4];
                ldsm4(bh, sb + 2 * T_SZ + nrow * GP + bcol);
                ldsm4(bl, sb + 3 * T_SZ + nrow * GP + bcol);
                #pragma unroll
                for (int mt = 0; mt < 2; mt++) {
                    mma16816(c[mt][2 * p], ah[mt], &bh[0]);
                    mma16816(c[mt][2 * p], ah[mt], &bl[0]);
                    mma16816(c[mt][2 * p], al[mt], &bh[0]);
                    mma16816(c[mt][2 * p + 1], ah[mt], &bh[2]);
                    mma16816(c[mt][2 * p + 1], ah[mt], &bl[2]);
                    mma16816(c[mt][2 * p + 1], al[mt], &bh[2]);
                }
            }
        }
    }

    int g = lane >> 2, t4 = lane & 3;
    #pragma unroll
    for (int mt = 0; mt < 2; mt++)
        #pragma unroll
        for (int nt = 0; nt < 8; nt++)
            #pragma unroll
            for (int e = 0; e < 4; e++) c[mt][nt][e] *= scale;

    if (MODE == 1) {
        // per-row max over this warp's 64-col head segment
        float rm[4] = {0.f, 0.f, 0.f, 0.f};
        #pragma unroll
        for (int mt = 0; mt < 2; mt++)
            #pragma unroll
            for (int nt = 0; nt < 8; nt++) {
                rm[mt * 2]     = fmaxf(rm[mt * 2],     fmaxf(fabsf(c[mt][nt][0]), fabsf(c[mt][nt][1])));
                rm[mt * 2 + 1] = fmaxf(rm[mt * 2 + 1], fmaxf(fabsf(c[mt][nt][2]), fabsf(c[mt][nt][3])));
            }
        #pragma unroll
        for (int i = 0; i < 4; i++) {
            rm[i] = fmaxf(rm[i], __shfl_xor_sync(~0u, rm[i], 1));
            rm[i] = fmaxf(rm[i], __shfl_xor_sync(~0u, rm[i], 2));
            rm[i] = fmaxf(rm[i], 1e-20f);
        }
        int head = (tn + wn * 64) >> 6;
        #pragma unroll
        for (int mt = 0; mt < 2; mt++)
            #pragma unroll
            for (int hf = 0; hf < 2; hf++) {
                int row = tm + wm * 32 + mt * 16 + g + hf * 8;
                if (t4 == 0) dqout[(size_t)head * ROWS + row] = rm[mt * 2 + hf] * (1.f / 127.f);
                float sq = 127.f / rm[mt * 2 + hf];
                #pragma unroll
                for (int nt = 0; nt < 8; nt++) {
                    float v0 = c[mt][nt][hf * 2] * sq, v1 = c[mt][nt][hf * 2 + 1] * sq;
                    float f10 = rintf(v0), f11 = rintf(v1);
                    float f20 = rintf((v0 - f10) * 254.f), f21 = rintf((v1 - f11) * 254.f);
                    int col = tn + wn * 64 + nt * 8 + t4 * 2;
                    size_t o = (size_t)row * DIM + col;
                    *(unsigned short*)&O1[o] = (unsigned short)(((int)f10 & 255) | (((int)f11 & 255) << 8));
                    *(unsigned short*)&O2[o] = (unsigned short)(((int)f20 & 255) | (((int)f21 & 255) << 8));
                }
            }
        return;
    }

    #pragma unroll
    for (int mt = 0; mt < 2; mt++)
        #pragma unroll
        for (int nt = 0; nt < 8; nt++) {
            int row = tm + wm * 32 + mt * 16 + g;
            int col = tn + wn * 64 + nt * 8 + t4 * 2;
            *(float2*)&Cf[(size_t)row * DIM + col]       = make_float2(c[mt][nt][0], c[mt][nt][1]);
            *(float2*)&Cf[(size_t)(row + 8) * DIM + col] = make_float2(c[mt][nt][2], c[mt][nt][3]);
        }

    if (MODE == 2) {
        #pragma unroll
        for (int nt = 0; nt < 8; nt++)
            #pragma unroll
            for (int par = 0; par < 2; par++) {
                float m = fmaxf(fmaxf(fabsf(c[0][nt][par]), fabsf(c[0][nt][par + 2])),
                                fmaxf(fabsf(c[1][nt][par]), fabsf(c[1][nt][par + 2])));
                m = fmaxf(m, __shfl_xor_sync(~0u, m, 4));
                m = fmaxf(m, __shfl_xor_sync(~0u, m, 8));
                m = fmaxf(m, __shfl_xor_sync(~0u, m, 16));
                if (lane < 4)
                    atomicMax(&g_vamax[tn + wn * 64 + nt * 8 + t4 * 2 + par], __float_as_int(m));
            }
    }
}

// ---------- transpose + quantize V -> VT[d][j] int8 2-slice ----------
__global__ __launch_bounds__(256) void tq_kernel(const float* __restrict__ V,
                                                 int8_t* __restrict__ VT1, int8_t* __restrict__ VT2) {
    __shared__ float ts[128][65];
    int bh = blockIdx.x, jc = blockIdx.y;
    int b = bh >> 3, h = bh & 7, tid = threadIdx.x;
    #pragma unroll
    for (int u = 0; u < 8; u++) {
        int idx = tid + u * 256;
        int row = idx >> 4, c4 = (idx & 15) * 4;
        float4 f = *(const float4*)&V[(size_t)(b * NSEQ + jc * 128 + row) * DIM + h * 64 + c4];
        ts[row][c4] = f.x; ts[row][c4 + 1] = f.y; ts[row][c4 + 2] = f.z; ts[row][c4 + 3] = f.w;
    }
    __syncthreads();
    int d = tid & 63, jg = (tid >> 6) * 32;
    float sv = 127.f / fmaxf(__int_as_float(g_vamax[h * 64 + d]), 1e-20f);
    uint32_t w1[8], w2[8];
    #pragma unroll
    for (int w = 0; w < 8; w++) {
        uint32_t a = 0, bb = 0;
        #pragma unroll
        for (int k = 0; k < 4; k++) {
            float v = ts[jg + w * 4 + k][d] * sv;
            float f1 = rintf(v), f2 = rintf((v - f1) * 254.f);
            a |= ((uint32_t)((int)f1 & 255)) << (8 * k);
            bb |= ((uint32_t)((int)f2 & 255)) << (8 * k);
        }
        w1[w] = a; w2[w] = bb;
    }
    size_t o = (size_t)(bh * 64 + d) * NSEQ + jc * 128 + jg;
    *(uint4*)&VT1[o] = make_uint4(w1[0], w1[1], w1[2], w1[3]);
    *(uint4*)&VT1[o + 16] = make_uint4(w1[4], w1[5], w1[6], w1[7]);
    *(uint4*)&VT2[o] = make_uint4(w2[0], w2[1], w2[2], w2[3]);
    *(uint4*)&VT2[o + 16] = make_uint4(w2[4], w2[5], w2[6], w2[7]);
}

// ---------- int8 flash attention ----------
#define AP 80
#define OK1 0
#define OK2 5120
#define OV1 10240
#define OV2 15360
#define OSK 20480
#define ST_SZ 20736
#define PB_OFF (2 * ST_SZ)
#define A_SMEM (PB_OFF + 8 * 2560)

__global__ __launch_bounds__(256, 1)
void attn_i8(const int8_t* __restrict__ Q1, const int8_t* __restrict__ Q2, const float* __restrict__ Qdq,
             const int8_t* __restrict__ K1, const int8_t* __restrict__ K2, const float* __restrict__ Kdq,
             const int8_t* __restrict__ VT1, const int8_t* __restrict__ VT2,
             __nv_bfloat16* __restrict__ Oh, __nv_bfloat16* __restrict__ Ol) {
    extern __shared__ char sm[];
    uint32_t sb = smem_u32(sm);
    int tid = threadIdx.x, lane = tid & 31, wd = tid >> 5;
    int bh = blockIdx.x, b = bh >> 3, h = bh & 7;
    int iBase = blockIdx.y * 128;
    int g = lane >> 2, t4 = lane & 3;

    // stage Q (int8, per-head 64B rows)
    #pragma unroll
    for (int u = 0; u < 2; u++) {
        int idx = tid + u * 256;
        int row = idx >> 2, c16 = (idx & 3) * 16;
        size_t ga = (size_t)(b * NSEQ + iBase + row) * DIM + h * DHEAD + c16;
        uint32_t d = sb + row * AP + c16;
        cpa16(d, &Q1[ga]); cpa16(d + 10240, &Q2[ga]);
    }
    CP_COMMIT(); CP_WAIT(0);
    __syncthreads();
    uint32_t q1f[2][4], q2f[2][4];
    {
        uint32_t arow = wd * 16 + (lane & 15);
        #pragma unroll
        for (int kc = 0; kc < 2; kc++) {
            uint32_t acol = kc * 32 + ((lane >> 4) << 4);
            ldsm4(q1f[kc], sb + arow * AP + acol);
            ldsm4(q2f[kc], sb + 10240 + arow * AP + acol);
        }
    }
    float dqr0 = Qdq[(size_t)h * ROWS + b * NSEQ + iBase + wd * 16 + g];
    float dqr1 = Qdq[(size_t)h * ROWS + b * NSEQ + iBase + wd * 16 + g + 8];
    __syncthreads();

    int oA[8][4], oB[8][4];
    #pragma unroll
    for (int i = 0; i < 8; i++)
        #pragma unroll
        for (int e = 0; e < 4; e++) { oA[i][e] = 0; oB[i][e] = 0; }
    float l0 = 0.f, l1 = 0.f;
    uint32_t pb1 = sb + PB_OFF + wd * 2560, pb2 = pb1 + 1280;
    int srow = tid >> 2, sc16 = (tid & 3) * 16;

    // prologue: stage j-block 0
    {
        size_t kg = (size_t)(b * NSEQ + srow) * DIM + h * DHEAD + sc16;
        size_t vg = (size_t)(bh * DHEAD + srow) * NSEQ + sc16;
        uint32_t d = sb + srow * AP + sc16;
        cpa16(d + OK1, &K1[kg]); cpa16(d + OK2, &K2[kg]);
        cpa16(d + OV1, &VT1[vg]); cpa16(d + OV2, &VT2[vg]);
        if (tid < 16) cpa16(sb + OSK + tid * 16, &Kdq[(size_t)h * ROWS + b * NSEQ + tid * 4]);
    }
    CP_COMMIT();

    for (int bi = 0; bi < 32; bi++) {
        if (bi < 31) {
            int j0 = (bi + 1) * 64;
            uint32_t d = sb + ((bi + 1) & 1) * ST_SZ + srow * AP + sc16;
            size_t kg = (size_t)(b * NSEQ + j0 + srow) * DIM + h * DHEAD + sc16;
            size_t vg = (size_t)(bh * DHEAD + srow) * NSEQ + j0 + sc16;
            cpa16(d + OK1, &K1[kg]); cpa16(d + OK2, &K2[kg]);
            cpa16(d + OV1, &VT1[vg]); cpa16(d + OV2, &VT2[vg]);
            if (tid < 16)
                cpa16(sb + ((bi + 1) & 1) * ST_SZ + OSK + tid * 16,
                      &Kdq[(size_t)h * ROWS + b * NSEQ + j0 + tid * 4]);
            CP_COMMIT(); CP_WAIT(1);
        } else {
            CP_WAIT(0);
        }
        __syncthreads();
        uint32_t stoff = (bi & 1) * ST_SZ;
        uint32_t buf = sb + stoff;

        // S = Q K^T (int)
        int sA[8][4], sB[8][4];
        #pragma unroll
        for (int i = 0; i < 8; i++)
            #pragma unroll
            for (int e = 0; e < 4; e++) { sA[i][e] = 0; sB[i][e] = 0; }
        uint32_t bro = ((lane >> 4) << 3) + (lane & 7);
        #pragma unroll
        for (int kc = 0; kc < 2; kc++) {
            uint32_t bcol = kc * 32 + (((lane >> 3) & 1) << 4);
            #pragma unroll
            for (int p = 0; p < 4; p++) {
                uint32_t nrow = p * 16 + bro;
                uint32_t b1[4], b2[4];
                ldsm4(b1, buf + OK1 + nrow * AP + bcol);
                ldsm4(b2, buf + OK2 + nrow * AP + bcol);
                imma(sA[2 * p], q1f[kc], &b1[0]);
                imma(sB[2 * p], q1f[kc], &b2[0]);
                imma(sB[2 * p], q2f[kc], &b1[0]);
                imma(sA[2 * p + 1], q1f[kc], &b1[2]);
                imma(sB[2 * p + 1], q1f[kc], &b2[2]);
                imma(sB[2 * p + 1], q2f[kc], &b1[2]);
            }
        }

        __syncwarp();
        // softmax (no-max) + fixed-scale 2-slice quantize of P into per-warp smem
        #pragma unroll
        for (int nt = 0; nt < 8; nt++) {
            float2 dk = *(const float2*)(sm + stoff + OSK + (nt * 8 + 2 * t4) * 4);
            float p0 = __expf(((float)sA[nt][0] + (float)sB[nt][0] * INV254) * dqr0 * dk.x);
            float p1 = __expf(((float)sA[nt][1] + (float)sB[nt][1] * INV254) * dqr0 * dk.y);
            float p2 = __expf(((float)sA[nt][2] + (float)sB[nt][2] * INV254) * dqr1 * dk.x);
            float p3 = __expf(((float)sA[nt][3] + (float)sB[nt][3] * INV254) * dqr1 * dk.y);
            l0 += p0 + p1; l1 += p2 + p3;
            float v0 = fminf(p0 * SPQ, 127.f), v1 = fminf(p1 * SPQ, 127.f);
            float v2 = fminf(p2 * SPQ, 127.f), v3 = fminf(p3 * SPQ, 127.f);
            float a0 = rintf(v0), a1 = rintf(v1), a2 = rintf(v2), a3 = rintf(v3);
            float r0 = rintf((v0 - a0) * 254.f), r1 = rintf((v1 - a1) * 254.f);
            float r2 = rintf((v2 - a2) * 254.f), r3 = rintf((v3 - a3) * 254.f);
            uint32_t co = nt * 8 + 2 * t4;
            sts16(pb1 + g * AP + co,        ((int)a0 & 255) | (((int)a1 & 255) << 8));
            sts16(pb1 + (g + 8) * AP + co,  ((int)a2 & 255) | (((int)a3 & 255) << 8));
            sts16(pb2 + g * AP + co,        ((int)r0 & 255) | (((int)r1 & 255) << 8));
            sts16(pb2 + (g + 8) * AP + co,  ((int)r2 & 255) | (((int)r3 & 255) << 8));
        }
        __syncwarp();

        // O += P V (persistent int accumulators)
        #pragma unroll
        for (int kc = 0; kc < 2; kc++) {
            uint32_t pa1[4], pa2[4];
            uint32_t acol = kc * 32 + ((lane >> 4) << 4);
            ldsm4(pa1, pb1 + (lane & 15) * AP + acol);
            ldsm4(pa2, pb2 + (lane & 15) * AP + acol);
            uint32_t bcol = kc * 32 + (((lane >> 3) & 1) << 4);
            #pragma unroll
            for (int dp = 0; dp < 4; dp++) {
                uint32_t nrow = dp * 16 + bro;
                uint32_t v1[4], v2[4];
                ldsm4(v1, buf + OV1 + nrow * AP + bcol);
                ldsm4(v2, buf + OV2 + nrow * AP + bcol);
                imma(oA[2 * dp], pa1, &v1[0]);
                imma(oB[2 * dp], pa1, &v2[0]);
                imma(oB[2 * dp], pa2, &v1[0]);
                imma(oA[2 * dp + 1], pa1, &v1[2]);
                imma(oB[2 * dp + 1], pa1, &v2[2]);
                imma(oB[2 * dp + 1], pa2, &v1[2]);
            }
        }
        __syncthreads();
    }

    l0 += __shfl_xor_sync(~0u, l0, 1); l0 += __shfl_xor_sync(~0u, l0, 2);
    l1 += __shfl_xor_sync(~0u, l1, 1); l1 += __shfl_xor_sync(~0u, l1, 2);
    float i0v = 1.f / l0, i1v = 1.f / l1;

    size_t base = (size_t)b * NSEQ * DIM + (size_t)h * DHEAD;
    size_t ga0 = base + (size_t)(iBase + wd * 16 + g) * DIM + t4 * 2;
    size_t ga1 = ga0 + 8 * DIM;
    const float FQ = 16.f / (127.f * 127.f);
    #pragma unroll
    for (int nt = 0; nt < 8; nt++) {
        int2 am = *(const int2*)&g_vamax[h * 64 + nt * 8 + 2 * t4];
        float f0 = __int_as_float(am.x) * FQ, f1 = __int_as_float(am.y) * FQ;
        float x0 = ((float)oA[nt][0] + (float)oB[nt][0] * INV254) * f0 * i0v;
        float x1 = ((float)oA[nt][1] + (float)oB[nt][1] * INV254) * f1 * i0v;
        float y0 = ((float)oA[nt][2] + (float)oB[nt][2] * INV254) * f0 * i1v;
        float y1 = ((float)oA[nt][3] + (float)oB[nt][3] * INV254) * f1 * i1v;
        *(uint32_t*)&Oh[ga0 + nt * 8] = bf2pack(x0, x1);
        *(uint32_t*)&Ol[ga0 + nt * 8] = bf2pack(bfres(x0), bfres(x1));
        *(uint32_t*)&Oh[ga1 + nt * 8] = bf2pack(y0, y1);
        *(uint32_t*)&Ol[ga1 + nt * 8] = bf2pack(bfres(y0), bfres(y1));
    }
}

// ---------- launch ----------
extern "C" void kernel_launch(void* const* d_in, const int* in_sizes, int n_in,
                              void* d_out, int out_size) {
    const float* x     = (const float*)d_in[0];
    const float* ln_w  = (const float*)d_in[1];
    const float* ln_b  = (const float*)d_in[2];
    const float* wq    = (const float*)d_in[3];
    const float* wk    = (const float*)d_in[4];
    const float* wv_v  = (const float*)d_in[5];
    const float* wv_g  = (const float*)d_in[6];
    const float* w_out = (const float*)d_in[7];
    float* out = (float*)d_out;

    __nv_bfloat16 *xnh, *xnl, *ath, *atl, *wqh, *wql, *wkh, *wkl, *wvh, *wvl, *woh, *wol;
    int8_t *q1, *q2, *k1, *k2, *vt1, *vt2;
    float *qdq, *kdq, *vv;
    cudaGetSymbolAddress((void**)&xnh, g_xnh); cudaGetSymbolAddress((void**)&xnl, g_xnl);
    cudaGetSymbolAddress((void**)&ath, g_ath); cudaGetSymbolAddress((void**)&atl, g_atl);
    cudaGetSymbolAddress((void**)&wqh, g_wqh); cudaGetSymbolAddress((void**)&wql, g_wql);
    cudaGetSymbolAddress((void**)&wkh, g_wkh); cudaGetSymbolAddress((void**)&wkl, g_wkl);
    cudaGetSymbolAddress((void**)&wvh, g_wvh); cudaGetSymbolAddress((void**)&wvl, g_wvl);
    cudaGetSymbolAddress((void**)&woh, g_woh); cudaGetSymbolAddress((void**)&wol, g_wol);
    cudaGetSymbolAddress((void**)&q1, g_q1); cudaGetSymbolAddress((void**)&q2, g_q2);
    cudaGetSymbolAddress((void**)&k1, g_k1); cudaGetSymbolAddress((void**)&k2, g_k2);
    cudaGetSymbolAddress((void**)&vt1, g_vt1); cudaGetSymbolAddress((void**)&vt2, g_vt2);
    cudaGetSymbolAddress((void**)&qdq, g_qdq); cudaGetSymbolAddress((void**)&kdq, g_kdq);
    cudaGetSymbolAddress((void**)&vv, g_v);

    cudaFuncSetAttribute(gemm_bf3<0>, cudaFuncAttributeMaxDynamicSharedMemorySize, G_SMEM);
    cudaFuncSetAttribute(gemm_bf3<1>, cudaFuncAttributeMaxDynamicSharedMemorySize, G_SMEM);
    cudaFuncSetAttribute(gemm_bf3<2>, cudaFuncAttributeMaxDynamicSharedMemorySize, G_SMEM);
    cudaFuncSetAttribute(attn_i8, cudaFuncAttributeMaxDynamicSharedMemorySize, A_SMEM);

    dim3 gg(DIM / 128, ROWS / 128);

    zero_amax<<<1, 512>>>();
    conv_kernel<<<(DIM * DIM + 255) / 256, 256>>>(wq, wqh, wql, DIM * DIM);
    ln_kernel<<<ROWS, 256>>>(x, ln_w, ln_b);
    gemm_bf3<1><<<gg, 256, G_SMEM>>>(xnh, xnl, wqh, wql, nullptr, q1, q2, qdq, 0.125f);

    conv_kernel<<<(DIM * DIM + 255) / 256, 256>>>(wk, wkh, wkl, DIM * DIM);
    gemm_bf3<1><<<gg, 256, G_SMEM>>>(xnh, xnl, wkh, wkl, nullptr, k1, k2, kdq, 1.0f);

    wnorm_kernel<<<DIM, 256>>>(wv_v, wv_g);
    gemm_bf3<2><<<gg, 256, G_SMEM>>>(xnh, xnl, wvh, wvl, vv, nullptr, nullptr, nullptr, 1.0f);
    tq_kernel<<<dim3(32, 16), 256>>>(vv, vt1, vt2);

    conv_kernel<<<(DIM * DIM + 255) / 256, 256>>>(w_out, woh, wol, DIM * DIM);

    attn_i8<<<dim3(32, 16), 256, A_SMEM>>>(q1, q2, qdq, k1, k2, kdq, vt1, vt2, ath, atl);

    gemm_bf3<0><<<gg, 256, G_SMEM>>>(ath, atl, woh, wol, out, nullptr, nullptr, nullptr, 1.0f);
}

// round 9
// speedup vs baseline: 2.2280x; 2.2280x over previous
#include <cuda_runtime.h>
#include <cuda_bf16.h>
#include <cstdint>

#define DIM 512
#define HEADS 8
#define DHEAD 64
#define BATCH 4
#define NSEQ 2048
#define ROWS (BATCH * NSEQ)   // 8192

// ================= scratch (no allocations allowed) =================
__device__ __nv_bfloat16 g_xnh[ROWS * DIM], g_xnl[ROWS * DIM];
__device__ __nv_bfloat16 g_qh[ROWS * DIM], g_ql[ROWS * DIM];
__device__ __nv_bfloat16 g_kh[ROWS * DIM], g_kl[ROWS * DIM];
__device__ __nv_bfloat16 g_vh[ROWS * DIM], g_vl[ROWS * DIM];
__device__ __nv_bfloat16 g_ath[ROWS * DIM], g_atl[ROWS * DIM];
__device__ __nv_bfloat16 g_wqh[DIM * DIM], g_wql[DIM * DIM];
__device__ __nv_bfloat16 g_wkh[DIM * DIM], g_wkl[DIM * DIM];
__device__ __nv_bfloat16 g_wvh[DIM * DIM], g_wvl[DIM * DIM];
__device__ __nv_bfloat16 g_woh[DIM * DIM], g_wol[DIM * DIM];

// ================= helpers =================
__device__ __forceinline__ uint32_t smem_u32(const void* p) {
    uint32_t a;
    asm("{ .reg .u64 t; cvta.to.shared.u64 t, %1; cvt.u32.u64 %0, t; }" : "=r"(a) : "l"(p));
    return a;
}
__device__ __forceinline__ void ldsm4(uint32_t* r, uint32_t a) {
    asm volatile("ldmatrix.sync.aligned.m8n8.x4.shared.b16 {%0,%1,%2,%3}, [%4];"
                 : "=r"(r[0]), "=r"(r[1]), "=r"(r[2]), "=r"(r[3]) : "r"(a));
}
__device__ __forceinline__ void ldsm4t(uint32_t* r, uint32_t a) {
    asm volatile("ldmatrix.sync.aligned.m8n8.x4.trans.shared.b16 {%0,%1,%2,%3}, [%4];"
                 : "=r"(r[0]), "=r"(r[1]), "=r"(r[2]), "=r"(r[3]) : "r"(a));
}
__device__ __forceinline__ void mma16816(float* c, const uint32_t* a, const uint32_t* b) {
    asm volatile("mma.sync.aligned.m16n8k16.row.col.f32.bf16.bf16.f32 "
                 "{%0,%1,%2,%3}, {%4,%5,%6,%7}, {%8,%9}, {%0,%1,%2,%3};"
                 : "+f"(c[0]), "+f"(c[1]), "+f"(c[2]), "+f"(c[3])
                 : "r"(a[0]), "r"(a[1]), "r"(a[2]), "r"(a[3]), "r"(b[0]), "r"(b[1]));
}
__device__ __forceinline__ void cpa16(uint32_t d, const void* s) {
    asm volatile("cp.async.cg.shared.global [%0], [%1], 16;" :: "r"(d), "l"(s));
}
#define CP_COMMIT() asm volatile("cp.async.commit_group;")
#define CP_WAIT(n)  asm volatile("cp.async.wait_group %0;" :: "n"(n))

__device__ __forceinline__ uint32_t bf2pack(float a, float b) {
    __nv_bfloat162 t = __floats2bfloat162_rn(a, b);
    return *reinterpret_cast<uint32_t*>(&t);
}
__device__ __forceinline__ float bfres(float a) {
    __nv_bfloat16 h = __float2bfloat16_rn(a);
    return a - __bfloat162float(h);
}

// ================= LayerNorm -> bf16 hi/lo =================
__global__ __launch_bounds__(256) void ln_kernel(const float* __restrict__ x,
                                                 const float* __restrict__ w,
                                                 const float* __restrict__ b) {
    __shared__ float sb1[8], sb2[8];
    int row = blockIdx.x, t = threadIdx.x;
    const float* xr = x + (size_t)row * DIM;
    float v0 = xr[t], v1 = xr[t + 256];
    float s = v0 + v1, ss = v0 * v0 + v1 * v1;
    #pragma unroll
    for (int o = 16; o > 0; o >>= 1) {
        s  += __shfl_xor_sync(~0u, s, o);
        ss += __shfl_xor_sync(~0u, ss, o);
    }
    int lane = t & 31, wd = t >> 5;
    if (lane == 0) { sb1[wd] = s; sb2[wd] = ss; }
    __syncthreads();
    if (wd == 0) {
        float r1 = (lane < 8) ? sb1[lane] : 0.f, r2 = (lane < 8) ? sb2[lane] : 0.f;
        #pragma unroll
        for (int o = 4; o > 0; o >>= 1) {
            r1 += __shfl_xor_sync(~0u, r1, o);
            r2 += __shfl_xor_sync(~0u, r2, o);
        }
        if (lane == 0) { sb1[0] = r1; sb2[0] = r2; }
    }
    __syncthreads();
    float mu  = sb1[0] * (1.f / DIM);
    float var = sb2[0] * (1.f / DIM) - mu * mu;
    float inv = rsqrtf(var + 1e-5f);
    float o0 = (v0 - mu) * inv * w[t] + b[t];
    float o1 = (v1 - mu) * inv * w[t + 256] + b[t + 256];
    size_t base = (size_t)row * DIM;
    __nv_bfloat16 h0 = __float2bfloat16_rn(o0), h1 = __float2bfloat16_rn(o1);
    g_xnh[base + t] = h0;        g_xnh[base + t + 256] = h1;
    g_xnl[base + t] = __float2bfloat16_rn(o0 - __bfloat162float(h0));
    g_xnl[base + t + 256] = __float2bfloat16_rn(o1 - __bfloat162float(h1));
}

// ================= weight-norm -> bf16 hi/lo =================
__global__ __launch_bounds__(256) void wnorm_kernel(const float* __restrict__ wv_v,
                                                    const float* __restrict__ wv_g) {
    __shared__ float sbuf[8];
    int row = blockIdx.x, t = threadIdx.x;
    const float* vr = wv_v + (size_t)row * DIM;
    float v0 = vr[t], v1 = vr[t + 256];
    float ss = v0 * v0 + v1 * v1;
    #pragma unroll
    for (int o = 16; o > 0; o >>= 1) ss += __shfl_xor_sync(~0u, ss, o);
    int lane = t & 31, wd = t >> 5;
    if (lane == 0) sbuf[wd] = ss;
    __syncthreads();
    if (wd == 0) {
        float r = (lane < 8) ? sbuf[lane] : 0.f;
        #pragma unroll
        for (int o = 4; o > 0; o >>= 1) r += __shfl_xor_sync(~0u, r, o);
        if (lane == 0) sbuf[0] = r;
    }
    __syncthreads();
    float sc = wv_g[row] * rsqrtf(sbuf[0]);
    float o0 = v0 * sc, o1 = v1 * sc;
    size_t base = (size_t)row * DIM;
    __nv_bfloat16 h0 = __float2bfloat16_rn(o0), h1 = __float2bfloat16_rn(o1);
    g_wvh[base + t] = h0;        g_wvh[base + t + 256] = h1;
    g_wvl[base + t] = __float2bfloat16_rn(o0 - __bfloat162float(h0));
    g_wvl[base + t + 256] = __float2bfloat16_rn(o1 - __bfloat162float(h1));
}

// ================= fp32 -> bf16 hi/lo =================
__global__ __launch_bounds__(256) void conv_kernel(const float* __restrict__ src,
                                                   __nv_bfloat16* __restrict__ hi,
                                                   __nv_bfloat16* __restrict__ lo, int n) {
    int i = blockIdx.x * 256 + threadIdx.x;
    if (i < n) {
        float f = src[i];
        __nv_bfloat16 h = __float2bfloat16_rn(f);
        hi[i] = h;
        lo[i] = __float2bfloat16_rn(f - __bfloat162float(h));
    }
}

// ================= GEMM: double-buffered k-loop =================
// 128x128 tile, BK=64, 8 warps (4m x 2n), hi/lo 3-mma split.
// smem: 2 stages x (AH,AL,BH,BL), each tile 128 x GP bytes.
#define GP 144
#define TT (128 * GP)        // 18432 per tile
#define ST (4 * TT)          // 73728 per stage
#define G_SMEM (2 * ST)      // 147456

template <bool BF16OUT>
__global__ __launch_bounds__(256, 1)
void gemm_bf3(const __nv_bfloat16* __restrict__ Ah, const __nv_bfloat16* __restrict__ Al,
              const __nv_bfloat16* __restrict__ Bh, const __nv_bfloat16* __restrict__ Bl,
              float* __restrict__ Cf, __nv_bfloat16* __restrict__ Ch,
              __nv_bfloat16* __restrict__ Cl, float scale) {
    extern __shared__ char sm[];
    uint32_t sb = smem_u32(sm);
    int tid = threadIdx.x, lane = tid & 31, wd = tid >> 5;
    int wm = wd & 3, wn = wd >> 2;
    int tm = blockIdx.y * 128, tn = blockIdx.x * 128;

    float c[2][8][4];
    #pragma unroll
    for (int i = 0; i < 2; i++)
        #pragma unroll
        for (int j = 0; j < 8; j++)
            #pragma unroll
            for (int e = 0; e < 4; e++) c[i][j][e] = 0.f;

    // prologue: stage kc=0 into buffer 0
    {
        #pragma unroll
        for (int u = 0; u < 4; u++) {
            int e = tid + u * 256;
            int r = e >> 3, c8 = (e & 7) * 8;
            uint32_t d = sb + (uint32_t)r * GP + c8 * 2;
            size_t ga = (size_t)(tm + r) * DIM + c8;
            size_t gb = (size_t)(tn + r) * DIM + c8;
            cpa16(d, &Ah[ga]);           cpa16(d + TT, &Al[ga]);
            cpa16(d + 2 * TT, &Bh[gb]);  cpa16(d + 3 * TT, &Bl[gb]);
        }
        CP_COMMIT();
    }

    for (int kc = 0; kc < 8; kc++) {
        if (kc < 7) {
            // prefetch kc+1 into the other stage
            int k0 = (kc + 1) * 64;
            uint32_t sbase = sb + ((kc + 1) & 1) * ST;
            #pragma unroll
            for (int u = 0; u < 4; u++) {
                int e = tid + u * 256;
                int r = e >> 3, c8 = (e & 7) * 8;
                uint32_t d = sbase + (uint32_t)r * GP + c8 * 2;
                size_t ga = (size_t)(tm + r) * DIM + k0 + c8;
                size_t gb = (size_t)(tn + r) * DIM + k0 + c8;
                cpa16(d, &Ah[ga]);           cpa16(d + TT, &Al[ga]);
                cpa16(d + 2 * TT, &Bh[gb]);  cpa16(d + 3 * TT, &Bl[gb]);
            }
            CP_COMMIT();
            CP_WAIT(1);
        } else {
            CP_WAIT(0);
        }
        __syncthreads();

        uint32_t buf = sb + (kc & 1) * ST;
        #pragma unroll
        for (int ks = 0; ks < 4; ks++) {
            uint32_t ah[2][4], al[2][4];
            uint32_t acol = ks * 32 + ((lane >> 4) << 4);
            #pragma unroll
            for (int mt = 0; mt < 2; mt++) {
                uint32_t arow = wm * 32 + mt * 16 + (lane & 15);
                ldsm4(ah[mt], buf + arow * GP + acol);
                ldsm4(al[mt], buf + TT + arow * GP + acol);
            }
            uint32_t bro = ((lane >> 4) << 3) + (lane & 7);
            uint32_t bcol = ks * 32 + (((lane >> 3) & 1) << 4);
            #pragma unroll
            for (int p = 0; p < 4; p++) {
                uint32_t nrow = wn * 64 + p * 16 + bro;
                uint32_t bh[4], bl[4];
                ldsm4(bh, buf + 2 * TT + nrow * GP + bcol);
                ldsm4(bl, buf + 3 * TT + nrow * GP + bcol);
                #pragma unroll
                for (int mt = 0; mt < 2; mt++) {
                    mma16816(c[mt][2 * p],     ah[mt], &bh[0]);
                    mma16816(c[mt][2 * p],     ah[mt], &bl[0]);
                    mma16816(c[mt][2 * p],     al[mt], &bh[0]);
                    mma16816(c[mt][2 * p + 1], ah[mt], &bh[2]);
                    mma16816(c[mt][2 * p + 1], ah[mt], &bl[2]);
                    mma16816(c[mt][2 * p + 1], al[mt], &bh[2]);
                }
            }
        }
        __syncthreads();   // done reading this stage before it is re-staged
    }

    int g = lane >> 2, t4 = lane & 3;
    #pragma unroll
    for (int mt = 0; mt < 2; mt++) {
        #pragma unroll
        for (int nt = 0; nt < 8; nt++) {
            int row = tm + wm * 32 + mt * 16 + g;
            int col = tn + wn * 64 + nt * 8 + t4 * 2;
            float x0 = c[mt][nt][0] * scale, x1 = c[mt][nt][1] * scale;
            float y0 = c[mt][nt][2] * scale, y1 = c[mt][nt][3] * scale;
            if (BF16OUT) {
                *(uint32_t*)&Ch[(size_t)row * DIM + col]       = bf2pack(x0, x1);
                *(uint32_t*)&Cl[(size_t)row * DIM + col]       = bf2pack(bfres(x0), bfres(x1));
                *(uint32_t*)&Ch[(size_t)(row + 8) * DIM + col] = bf2pack(y0, y1);
                *(uint32_t*)&Cl[(size_t)(row + 8) * DIM + col] = bf2pack(bfres(y0), bfres(y1));
            } else {
                *(float2*)&Cf[(size_t)row * DIM + col]       = make_float2(x0, x1);
                *(float2*)&Cf[(size_t)(row + 8) * DIM + col] = make_float2(y0, y1);
            }
        }
    }
}

// ================= flash attention: 64-row j-tiles, occ 2 (R6, proven) =================
#define AST (64 * GP)           // 9216 per tile
#define A_SMEM (2 * 4 * AST)    // 73728
#define QL_OFF (128 * GP)

__global__ __launch_bounds__(256, 2)
void attn_mma(const __nv_bfloat16* __restrict__ Qh, const __nv_bfloat16* __restrict__ Ql,
              const __nv_bfloat16* __restrict__ Kh, const __nv_bfloat16* __restrict__ Kl,
              const __nv_bfloat16* __restrict__ Vh, const __nv_bfloat16* __restrict__ Vl,
              __nv_bfloat16* __restrict__ Oh, __nv_bfloat16* __restrict__ Ol) {
    extern __shared__ char sm[];
    uint32_t sb = smem_u32(sm);
    int tid = threadIdx.x, lane = tid & 31, wd = tid >> 5;
    int b = blockIdx.x >> 3, h = blockIdx.x & 7;
    int iBase = blockIdx.y * 128;
    size_t base = (size_t)b * NSEQ * DIM + (size_t)h * DHEAD;

    #pragma unroll
    for (int u = 0; u < 4; u++) {
        int e = tid + u * 256;
        int r = e >> 3, c8 = (e & 7) * 8;
        uint32_t d = sb + (uint32_t)r * GP + c8 * 2;
        size_t ga = base + (size_t)(iBase + r) * DIM + c8;
        cpa16(d, &Qh[ga]);
        cpa16(d + QL_OFF, &Ql[ga]);
    }
    CP_COMMIT(); CP_WAIT(0);
    __syncthreads();

    uint32_t qh[4][4], ql[4][4];
    {
        uint32_t arow = wd * 16 + (lane & 15);
        #pragma unroll
        for (int ks = 0; ks < 4; ks++) {
            uint32_t acol = ks * 32 + ((lane >> 4) << 4);
            ldsm4(qh[ks], sb + arow * GP + acol);
            ldsm4(ql[ks], sb + QL_OFF + arow * GP + acol);
        }
    }
    __syncthreads();

    float o[8][4];
    #pragma unroll
    for (int i = 0; i < 8; i++)
        #pragma unroll
        for (int e = 0; e < 4; e++) o[i][e] = 0.f;
    float l0 = 0.f, l1 = 0.f;

    #pragma unroll
    for (int u = 0; u < 2; u++) {
        int e = tid + u * 256;
        int r = e >> 3, c8 = (e & 7) * 8;
        uint32_t d = sb + (uint32_t)r * GP + c8 * 2;
        size_t ga = base + (size_t)r * DIM + c8;
        cpa16(d + 0 * AST, &Kh[ga]);
        cpa16(d + 1 * AST, &Kl[ga]);
        cpa16(d + 2 * AST, &Vh[ga]);
        cpa16(d + 3 * AST, &Vl[ga]);
    }
    CP_COMMIT();

    for (int bi = 0; bi < 32; bi++) {
        if (bi < 31) {
            uint32_t sbuf = sb + ((bi + 1) & 1) * 4 * AST;
            int j0 = (bi + 1) * 64;
            #pragma unroll
            for (int u = 0; u < 2; u++) {
                int e = tid + u * 256;
                int r = e >> 3, c8 = (e & 7) * 8;
                uint32_t d = sbuf + (uint32_t)r * GP + c8 * 2;
                size_t ga = base + (size_t)(j0 + r) * DIM + c8;
                cpa16(d + 0 * AST, &Kh[ga]);
                cpa16(d + 1 * AST, &Kl[ga]);
                cpa16(d + 2 * AST, &Vh[ga]);
                cpa16(d + 3 * AST, &Vl[ga]);
            }
            CP_COMMIT();
            CP_WAIT(1);
        } else {
            CP_WAIT(0);
        }
        __syncthreads();

        uint32_t buf = sb + (bi & 1) * 4 * AST;

        float s[8][4];
        #pragma unroll
        for (int nt = 0; nt < 8; nt++)
            #pragma unroll
            for (int e = 0; e < 4; e++) s[nt][e] = 0.f;

        uint32_t bro = ((lane >> 4) << 3) + (lane & 7);
        #pragma unroll
        for (int ks = 0; ks < 4; ks++) {
            uint32_t bcol = ks * 32 + (((lane >> 3) & 1) << 4);
            #pragma unroll
            for (int p = 0; p < 4; p++) {
                uint32_t nrow = p * 16 + bro;
                uint32_t bh[4], bl[4];
                ldsm4(bh, buf + 0 * AST + nrow * GP + bcol);
                ldsm4(bl, buf + 1 * AST + nrow * GP + bcol);
                mma16816(s[2 * p],     qh[ks], &bh[0]);
                mma16816(s[2 * p],     qh[ks], &bl[0]);
                mma16816(s[2 * p],     ql[ks], &bh[0]);
                mma16816(s[2 * p + 1], qh[ks], &bh[2]);
                mma16816(s[2 * p + 1], qh[ks], &bl[2]);
                mma16816(s[2 * p + 1], ql[ks], &bh[2]);
            }
        }

        #pragma unroll
        for (int nt = 0; nt < 8; nt++) {
            s[nt][0] = __expf(s[nt][0]);
            s[nt][1] = __expf(s[nt][1]);
            s[nt][2] = __expf(s[nt][2]);
            s[nt][3] = __expf(s[nt][3]);
            l0 += s[nt][0] + s[nt][1];
            l1 += s[nt][2] + s[nt][3];
        }

        uint32_t vro = (((lane >> 3) & 1) << 3) + (lane & 7);
        uint32_t vco = (lane >> 4) << 4;
        #pragma unroll
        for (int st = 0; st < 4; st++) {
            uint32_t a_h[4], a_l[4];
            a_h[0] = bf2pack(s[2 * st][0], s[2 * st][1]);
            a_h[1] = bf2pack(s[2 * st][2], s[2 * st][3]);
            a_h[2] = bf2pack(s[2 * st + 1][0], s[2 * st + 1][1]);
            a_h[3] = bf2pack(s[2 * st + 1][2], s[2 * st + 1][3]);
            a_l[0] = bf2pack(bfres(s[2 * st][0]), bfres(s[2 * st][1]));
            a_l[1] = bf2pack(bfres(s[2 * st][2]), bfres(s[2 * st][3]));
            a_l[2] = bf2pack(bfres(s[2 * st + 1][0]), bfres(s[2 * st + 1][1]));
            a_l[3] = bf2pack(bfres(s[2 * st + 1][2]), bfres(s[2 * st + 1][3]));
            uint32_t jrow = st * 16 + vro;
            #pragma unroll
            for (int dp = 0; dp < 4; dp++) {
                uint32_t db = dp * 32 + vco;
                uint32_t vh[4], vl[4];
                ldsm4t(vh, buf + 2 * AST + jrow * GP + db);
                ldsm4t(vl, buf + 3 * AST + jrow * GP + db);
                mma16816(o[2 * dp],     a_h, &vh[0]);
                mma16816(o[2 * dp],     a_h, &vl[0]);
                mma16816(o[2 * dp],     a_l, &vh[0]);
                mma16816(o[2 * dp + 1], a_h, &vh[2]);
                mma16816(o[2 * dp + 1], a_h, &vl[2]);
                mma16816(o[2 * dp + 1], a_l, &vh[2]);
            }
        }
        __syncthreads();
    }

    l0 += __shfl_xor_sync(~0u, l0, 1); l0 += __shfl_xor_sync(~0u, l0, 2);
    l1 += __shfl_xor_sync(~0u, l1, 1); l1 += __shfl_xor_sync(~0u, l1, 2);
    float i0v = 1.f / l0, i1v = 1.f / l1;

    int g = lane >> 2, t4 = lane & 3;
    size_t ga0 = base + (size_t)(iBase + wd * 16 + g) * DIM + t4 * 2;
    size_t ga1 = ga0 + 8 * DIM;
    #pragma unroll
    for (int dt = 0; dt < 8; dt++) {
        float x0 = o[dt][0] * i0v, x1 = o[dt][1] * i0v;
        float y0 = o[dt][2] * i1v, y1 = o[dt][3] * i1v;
        *(uint32_t*)&Oh[ga0 + dt * 8] = bf2pack(x0, x1);
        *(uint32_t*)&Ol[ga0 + dt * 8] = bf2pack(bfres(x0), bfres(x1));
        *(uint32_t*)&Oh[ga1 + dt * 8] = bf2pack(y0, y1);
        *(uint32_t*)&Ol[ga1 + dt * 8] = bf2pack(bfres(y0), bfres(y1));
    }
}

// ================= launch =================
extern "C" void kernel_launch(void* const* d_in, const int* in_sizes, int n_in,
                              void* d_out, int out_size) {
    const float* x     = (const float*)d_in[0];
    const float* ln_w  = (const float*)d_in[1];
    const float* ln_b  = (const float*)d_in[2];
    const float* wq    = (const float*)d_in[3];
    const float* wk    = (const float*)d_in[4];
    const float* wv_v  = (const float*)d_in[5];
    const float* wv_g  = (const float*)d_in[6];
    const float* w_out = (const float*)d_in[7];
    float* out = (float*)d_out;

    __nv_bfloat16 *xnh, *xnl, *ath, *atl;
    __nv_bfloat16 *qh, *ql, *kh, *kl, *vh, *vl;
    __nv_bfloat16 *wqh, *wql, *wkh, *wkl, *wvh, *wvl, *woh, *wol;
    cudaGetSymbolAddress((void**)&xnh, g_xnh); cudaGetSymbolAddress((void**)&xnl, g_xnl);
    cudaGetSymbolAddress((void**)&ath, g_ath); cudaGetSymbolAddress((void**)&atl, g_atl);
    cudaGetSymbolAddress((void**)&qh, g_qh); cudaGetSymbolAddress((void**)&ql, g_ql);
    cudaGetSymbolAddress((void**)&kh, g_kh); cudaGetSymbolAddress((void**)&kl, g_kl);
    cudaGetSymbolAddress((void**)&vh, g_vh); cudaGetSymbolAddress((void**)&vl, g_vl);
    cudaGetSymbolAddress((void**)&wqh, g_wqh); cudaGetSymbolAddress((void**)&wql, g_wql);
    cudaGetSymbolAddress((void**)&wkh, g_wkh); cudaGetSymbolAddress((void**)&wkl, g_wkl);
    cudaGetSymbolAddress((void**)&wvh, g_wvh); cudaGetSymbolAddress((void**)&wvl, g_wvl);
    cudaGetSymbolAddress((void**)&woh, g_woh); cudaGetSymbolAddress((void**)&wol, g_wol);

    cudaFuncSetAttribute(gemm_bf3<true>,  cudaFuncAttributeMaxDynamicSharedMemorySize, G_SMEM);
    cudaFuncSetAttribute(gemm_bf3<false>, cudaFuncAttributeMaxDynamicSharedMemorySize, G_SMEM);
    cudaFuncSetAttribute(attn_mma, cudaFuncAttributeMaxDynamicSharedMemorySize, A_SMEM);

    dim3 gg(DIM / 128, ROWS / 128);  // (4, 64)

    conv_kernel<<<(DIM * DIM + 255) / 256, 256>>>(wq, wqh, wql, DIM * DIM);
    ln_kernel<<<ROWS, 256>>>(x, ln_w, ln_b);
    gemm_bf3<true><<<gg, 256, G_SMEM>>>(xnh, xnl, wqh, wql, nullptr, qh, ql, 0.125f);

    conv_kernel<<<(DIM * DIM + 255) / 256, 256>>>(wk, wkh, wkl, DIM * DIM);
    gemm_bf3<true><<<gg, 256, G_SMEM>>>(xnh, xnl, wkh, wkl, nullptr, kh, kl, 1.0f);

    wnorm_kernel<<<DIM, 256>>>(wv_v, wv_g);
    gemm_bf3<true><<<gg, 256, G_SMEM>>>(xnh, xnl, wvh, wvl, nullptr, vh, vl, 1.0f);

    conv_kernel<<<(DIM * DIM + 255) / 256, 256>>>(w_out, woh, wol, DIM * DIM);

    attn_mma<<<dim3(32, 16), 256, A_SMEM>>>(qh, ql, kh, kl, vh, vl, ath, atl);

    gemm_bf3<false><<<gg, 256, G_SMEM>>>(ath, atl, woh, wol, out, nullptr, nullptr, 1.0f);
}